// round 3
// baseline (speedup 1.0000x reference)
#include <cuda_runtime.h>
#include <cuda_bf16.h>
#include <cstdint>

#define KN      100000     // nodes
#define KE      1600000    // edges
#define KIN     256        // in channels
#define KED     64         // edge dim
#define KH      4          // heads
#define KC      32         // channels/head
#define KHC     128        // H*C
#define KNB     ((KE + 31) / 32)   // scatter blocks

#define FULLM 0xFFFFFFFFu

// ---------------- scratch (static device globals; no allocation) ----------------
__device__ float4 g_xproj[KN * 32];        // [N][128] as float4   (51.2 MB)
__device__ float4 g_asrc[KN];              // [N][4]
__device__ float4 g_adst[KN];              // [N][4]
__device__ float  g_W2[KED * KH];          // [64][4]
__device__ float  g_loopsum[KH];
__device__ float  g_loopae[KH];
__device__ int    g_deg[KN];
__device__ int    g_off[KN + 1];
__device__ int    g_cursor[KN];
__device__ int    g_ssrc[KE];
__device__ float4 g_salpha[KE];            // [E][4]  (25.6 MB)
__device__ float4 g_part[KNB];             // per-block p-sums

// ---------------- helpers ----------------
__device__ __forceinline__ uint32_t smem_u32(const void* p) {
    return (uint32_t)__cvta_generic_to_shared(p);
}
__device__ __forceinline__ void ldsm_x4(uint32_t& r0, uint32_t& r1, uint32_t& r2, uint32_t& r3,
                                        uint32_t addr) {
    asm volatile("ldmatrix.sync.aligned.m8n8.x4.shared.b16 {%0,%1,%2,%3}, [%4];\n"
                 : "=r"(r0), "=r"(r1), "=r"(r2), "=r"(r3) : "r"(addr));
}
__device__ __forceinline__ void ldsm_x4_t(uint32_t& r0, uint32_t& r1, uint32_t& r2, uint32_t& r3,
                                          uint32_t addr) {
    asm volatile("ldmatrix.sync.aligned.m8n8.x4.trans.shared.b16 {%0,%1,%2,%3}, [%4];\n"
                 : "=r"(r0), "=r"(r1), "=r"(r2), "=r"(r3) : "r"(addr));
}
__device__ __forceinline__ void mma16816(float* d, const uint32_t* a, uint32_t b0, uint32_t b1) {
    asm volatile(
        "mma.sync.aligned.m16n8k16.row.col.f32.bf16.bf16.f32 "
        "{%0,%1,%2,%3},{%4,%5,%6,%7},{%8,%9},{%0,%1,%2,%3};\n"
        : "+f"(d[0]), "+f"(d[1]), "+f"(d[2]), "+f"(d[3])
        : "r"(a[0]), "r"(a[1]), "r"(a[2]), "r"(a[3]), "r"(b0), "r"(b1));
}

// ---------------- reset ----------------
__global__ void k_reset(int n) {
    int i = blockIdx.x * blockDim.x + threadIdx.x;
    if (i < n) g_deg[i] = 0;
    if (i < KH) g_loopsum[i] = 0.f;
}

// ---------------- W2[d][h] = sum_c W_edge[d, h*32+c] * att_edge[h, c] ----------------
__global__ void k_w2(const float* __restrict__ W_edge, const float* __restrict__ att_edge) {
    int t = threadIdx.x;                 // 256 threads
    int d = t >> 2, h = t & 3;
    float s = 0.f;
    #pragma unroll 8
    for (int c = 0; c < KC; c++)
        s += W_edge[d * KHC + h * KC + c] * att_edge[h * KC + c];
    g_W2[d * KH + h] = s;
}

// ---------------- GEMM: x_proj = x[N,256] @ W[256,128] via bf16-split HMMA ----------------
// Block: 256 thr = 8 warps (4x2). Tile M=128, N=128, k-chunk 32.
// Precision: x = hi + lo (bf16 each), W = hi + lo; acc += ah*bh + ah*bl + al*bh.
#define APAD 40
#define BPAD 136
__global__ __launch_bounds__(256) void k_gemm(const float* __restrict__ x,
                                              const float* __restrict__ W, int n) {
    __shared__ __nv_bfloat16 As[2][128][APAD];   // [part][m][k]
    __shared__ __nv_bfloat16 Bs[2][32][BPAD];    // [part][k][n]

    int tid = threadIdx.x;
    int lane = tid & 31;
    int wid = tid >> 5;
    int warp_m = wid & 3, warp_n = wid >> 1 >> 1 >> 0;  // wid>>2
    warp_n = wid >> 2;
    int m0 = warp_m * 32;
    int n0w = warp_n * 64;
    int bm = blockIdx.x * 128;
    int g = lane >> 2, t = lane & 3;

    float acc[2][8][4];
    #pragma unroll
    for (int mi = 0; mi < 2; mi++)
        #pragma unroll
        for (int ni = 0; ni < 8; ni++)
            #pragma unroll
            for (int r = 0; r < 4; r++) acc[mi][ni][r] = 0.f;

    // lane-dependent ldmatrix address components
    int a_row = (lane & 15);              // within 16-row atom
    int a_koff = (lane >> 4) * 8;
    int b_krow = (lane & 7) + ((lane >> 3) & 1) * 8;
    int b_noff = (lane >> 4) * 8;

    for (int kb = 0; kb < KIN; kb += 32) {
        // ---- load & convert A chunk: x[bm:bm+128][kb:kb+32] ----
        #pragma unroll
        for (int pp = 0; pp < 4; pp++) {
            int f = tid + pp * 256;
            int row = f >> 3, q = f & 7;
            int gm = bm + row;
            float4 v = make_float4(0.f, 0.f, 0.f, 0.f);
            if (gm < n) v = *(const float4*)(x + (size_t)gm * KIN + kb + q * 4);
            float vv[4] = {v.x, v.y, v.z, v.w};
            __nv_bfloat16 h[4], l[4];
            #pragma unroll
            for (int j = 0; j < 4; j++) {
                h[j] = __float2bfloat16(vv[j]);
                l[j] = __float2bfloat16(vv[j] - __bfloat162float(h[j]));
            }
            __nv_bfloat162 h01, h23, l01, l23;
            h01.x = h[0]; h01.y = h[1]; h23.x = h[2]; h23.y = h[3];
            l01.x = l[0]; l01.y = l[1]; l23.x = l[2]; l23.y = l[3];
            *(__nv_bfloat162*)&As[0][row][q * 4]     = h01;
            *(__nv_bfloat162*)&As[0][row][q * 4 + 2] = h23;
            *(__nv_bfloat162*)&As[1][row][q * 4]     = l01;
            *(__nv_bfloat162*)&As[1][row][q * 4 + 2] = l23;
        }
        // ---- load & convert B chunk: W[kb:kb+32][0:128] ----
        #pragma unroll
        for (int pp = 0; pp < 4; pp++) {
            int f = tid + pp * 256;
            int k = f >> 5, nq = (f & 31) * 4;
            float4 v = *(const float4*)(W + (size_t)(kb + k) * KHC + nq);
            float vv[4] = {v.x, v.y, v.z, v.w};
            __nv_bfloat16 h[4], l[4];
            #pragma unroll
            for (int j = 0; j < 4; j++) {
                h[j] = __float2bfloat16(vv[j]);
                l[j] = __float2bfloat16(vv[j] - __bfloat162float(h[j]));
            }
            __nv_bfloat162 h01, h23, l01, l23;
            h01.x = h[0]; h01.y = h[1]; h23.x = h[2]; h23.y = h[3];
            l01.x = l[0]; l01.y = l[1]; l23.x = l[2]; l23.y = l[3];
            *(__nv_bfloat162*)&Bs[0][k][nq]     = h01;
            *(__nv_bfloat162*)&Bs[0][k][nq + 2] = h23;
            *(__nv_bfloat162*)&Bs[1][k][nq]     = l01;
            *(__nv_bfloat162*)&Bs[1][k][nq + 2] = l23;
        }
        __syncthreads();

        #pragma unroll
        for (int ka = 0; ka < 2; ka++) {
            int k0 = ka * 16;
            // A fragments: [part][mi][4]
            uint32_t afrag[2][2][4];
            #pragma unroll
            for (int part = 0; part < 2; part++)
                #pragma unroll
                for (int mi = 0; mi < 2; mi++) {
                    uint32_t addr = smem_u32(&As[part][m0 + mi * 16 + a_row][k0 + a_koff]);
                    ldsm_x4(afrag[part][mi][0], afrag[part][mi][1],
                            afrag[part][mi][2], afrag[part][mi][3], addr);
                }
            // B fragments per npair, immediately consumed
            #pragma unroll
            for (int np = 0; np < 4; np++) {
                uint32_t bh[4], bl[4];
                {
                    uint32_t addr = smem_u32(&Bs[0][k0 + b_krow][n0w + np * 16 + b_noff]);
                    ldsm_x4_t(bh[0], bh[1], bh[2], bh[3], addr);
                }
                {
                    uint32_t addr = smem_u32(&Bs[1][k0 + b_krow][n0w + np * 16 + b_noff]);
                    ldsm_x4_t(bl[0], bl[1], bl[2], bl[3], addr);
                }
                #pragma unroll
                for (int half = 0; half < 2; half++) {
                    int ni = np * 2 + half;
                    #pragma unroll
                    for (int mi = 0; mi < 2; mi++) {
                        mma16816(acc[mi][ni], afrag[0][mi], bh[half * 2], bh[half * 2 + 1]);
                        mma16816(acc[mi][ni], afrag[0][mi], bl[half * 2], bl[half * 2 + 1]);
                        mma16816(acc[mi][ni], afrag[1][mi], bh[half * 2], bh[half * 2 + 1]);
                    }
                }
            }
        }
        __syncthreads();
    }

    // ---- epilogue ----
    float* gx = (float*)g_xproj;
    #pragma unroll
    for (int mi = 0; mi < 2; mi++) {
        #pragma unroll
        for (int ni = 0; ni < 8; ni++) {
            int col = n0w + ni * 8 + t * 2;
            int r0 = bm + m0 + mi * 16 + g;
            int r1 = r0 + 8;
            if (r0 < n) {
                float2 v; v.x = acc[mi][ni][0]; v.y = acc[mi][ni][1];
                *(float2*)&gx[(size_t)r0 * KHC + col] = v;
            }
            if (r1 < n) {
                float2 v; v.x = acc[mi][ni][2]; v.y = acc[mi][ni][3];
                *(float2*)&gx[(size_t)r1 * KHC + col] = v;
            }
        }
    }
}

// ---------------- a_src / a_dst: warp per node ----------------
__global__ void k_attn(const float* __restrict__ att_src,
                       const float* __restrict__ att_dst, int n) {
    int warp = (blockIdx.x * blockDim.x + threadIdx.x) >> 5;
    int lane = threadIdx.x & 31;
    if (warp >= n) return;
    float4 xp = g_xproj[(size_t)warp * 32 + lane];
    float4 as = *(const float4*)(att_src + lane * 4);
    float4 ad = *(const float4*)(att_dst + lane * 4);
    float ds = xp.x * as.x + xp.y * as.y + xp.z * as.z + xp.w * as.w;
    float dd = xp.x * ad.x + xp.y * ad.y + xp.z * ad.z + xp.w * ad.w;
    #pragma unroll
    for (int m = 1; m <= 4; m <<= 1) {
        ds += __shfl_xor_sync(FULLM, ds, m);
        dd += __shfl_xor_sync(FULLM, dd, m);
    }
    if ((lane & 7) == 0) {
        int h = lane >> 3;
        ((float*)&g_asrc[warp])[h] = ds;
        ((float*)&g_adst[warp])[h] = dd;
    }
}

// ---------------- histogram of dst ----------------
__global__ void k_hist(const int* __restrict__ edge_index, int E) {
    int e = blockIdx.x * blockDim.x + threadIdx.x;
    if (e < E) atomicAdd(&g_deg[edge_index[E + e]], 1);
}

// ---------------- single-block scan ----------------
__global__ void k_scan(int n) {
    __shared__ int s[1024];
    int t = threadIdx.x;
    int chunk = (n + 1023) / 1024;
    int start = t * chunk;
    int sum = 0;
    for (int j = 0; j < chunk; j++) {
        int i = start + j;
        if (i < n) sum += g_deg[i];
    }
    s[t] = sum;
    __syncthreads();
    for (int o = 1; o < 1024; o <<= 1) {
        int v = (t >= o) ? s[t - o] : 0;
        __syncthreads();
        s[t] += v;
        __syncthreads();
    }
    int run = s[t] - sum;
    for (int j = 0; j < chunk; j++) {
        int i = start + j;
        if (i < n) {
            g_off[i] = run;
            g_cursor[i] = run;
            run += g_deg[i];
        }
    }
    if (t == 1023) g_off[n] = s[1023];
}

// ---------------- scatter: 8 lanes per edge (4 edges/warp) ----------------
__global__ __launch_bounds__(256) void k_scatter(const int* __restrict__ edge_index,
                                                 const float* __restrict__ edge_attr, int E) {
    __shared__ float Ws2[KED * KH];
    __shared__ float bp[KH];
    int tid = threadIdx.x;
    Ws2[tid] = g_W2[tid];
    if (tid < KH) bp[tid] = 0.f;
    __syncthreads();

    int lane = tid & 31;
    int wid = tid >> 5;
    int g8 = lane >> 3, l8 = lane & 7;
    int e = blockIdx.x * 32 + wid * 4 + g8;

    float p0 = 0.f, p1 = 0.f, p2 = 0.f, p3 = 0.f;
    if (e < E) {
        const float* ea = edge_attr + (size_t)e * KED + l8 * 8;
        float4 v0 = *(const float4*)ea;
        float4 v1 = *(const float4*)(ea + 4);
        float av[8] = {v0.x, v0.y, v0.z, v0.w, v1.x, v1.y, v1.z, v1.w};
        int db = l8 * 8;
        #pragma unroll
        for (int j = 0; j < 8; j++) {
            const float* w = &Ws2[(db + j) * 4];
            p0 += av[j] * w[0];
            p1 += av[j] * w[1];
            p2 += av[j] * w[2];
            p3 += av[j] * w[3];
        }
    }
    #pragma unroll
    for (int m = 1; m <= 4; m <<= 1) {
        p0 += __shfl_xor_sync(FULLM, p0, m);
        p1 += __shfl_xor_sync(FULLM, p1, m);
        p2 += __shfl_xor_sync(FULLM, p2, m);
        p3 += __shfl_xor_sync(FULLM, p3, m);
    }
    if (l8 == 0 && e < E) {
        atomicAdd(&bp[0], p0);
        atomicAdd(&bp[1], p1);
        atomicAdd(&bp[2], p2);
        atomicAdd(&bp[3], p3);
        int src = edge_index[e];
        int dst = edge_index[E + e];
        float4 as = g_asrc[src];
        int pos = atomicAdd(&g_cursor[dst], 1);
        g_ssrc[pos] = src;
        g_salpha[pos] = make_float4(as.x + p0, as.y + p1, as.z + p2, as.w + p3);
    }
    __syncthreads();
    if (tid < KH) ((float*)&g_part[blockIdx.x])[tid] = bp[tid];
}

// ---------------- reduce per-block p-sums ----------------
__global__ void k_psum(int nb) {
    int tid = blockIdx.x * blockDim.x + threadIdx.x;
    int stride = gridDim.x * blockDim.x;
    float4 s = make_float4(0.f, 0.f, 0.f, 0.f);
    for (int j = tid; j < nb; j += stride) {
        float4 v = g_part[j];
        s.x += v.x; s.y += v.y; s.z += v.z; s.w += v.w;
    }
    #pragma unroll
    for (int m = 16; m >= 1; m >>= 1) {
        s.x += __shfl_xor_sync(FULLM, s.x, m);
        s.y += __shfl_xor_sync(FULLM, s.y, m);
        s.z += __shfl_xor_sync(FULLM, s.z, m);
        s.w += __shfl_xor_sync(FULLM, s.w, m);
    }
    __shared__ float4 ws[8];
    int warp = threadIdx.x >> 5;
    int lane = threadIdx.x & 31;
    if (lane == 0) ws[warp] = s;
    __syncthreads();
    if (warp == 0) {
        float4 v = (lane < 8) ? ws[lane] : make_float4(0.f, 0.f, 0.f, 0.f);
        #pragma unroll
        for (int m = 4; m >= 1; m >>= 1) {
            v.x += __shfl_xor_sync(FULLM, v.x, m);
            v.y += __shfl_xor_sync(FULLM, v.y, m);
            v.z += __shfl_xor_sync(FULLM, v.z, m);
            v.w += __shfl_xor_sync(FULLM, v.w, m);
        }
        if (lane == 0) {
            atomicAdd(&g_loopsum[0], v.x);
            atomicAdd(&g_loopsum[1], v.y);
            atomicAdd(&g_loopsum[2], v.z);
            atomicAdd(&g_loopsum[3], v.w);
        }
    }
}

// ---------------- loop a_edge = psum / E ----------------
__global__ void k_loopae(int E) {
    int h = threadIdx.x;
    if (h < KH) g_loopae[h] = g_loopsum[h] / (float)E;
}

// ---------------- aggregation: warp per node, fused softmax + weighted sum ----------------
__global__ __launch_bounds__(256) void k_agg(const float* __restrict__ bias,
                                             float* __restrict__ out, int n) {
    int i = (blockIdx.x * blockDim.x + threadIdx.x) >> 5;
    int lane = threadIdx.x & 31;
    if (i >= n) return;

    int hl = lane >> 3;     // head for accumulation lanes
    int sub = lane & 3;     // head for exp lanes

    float adst_s = ((const float*)&g_adst[i])[sub];
    float asrc_s = ((const float*)&g_asrc[i])[sub];
    float lae_s  = g_loopae[sub];
    float4 xpi = g_xproj[(size_t)i * 32 + lane];

    float4 acc = make_float4(0.f, 0.f, 0.f, 0.f);
    float dsum = 0.f;

    // self loop
    float vs = asrc_s + adst_s + lae_s;
    vs = vs > 0.f ? vs : 0.2f * vs;
    float ws = __expf(vs);
    if (lane < 4) dsum += ws;
    {
        float w = __shfl_sync(FULLM, ws, hl);
        acc.x += w * xpi.x; acc.y += w * xpi.y; acc.z += w * xpi.z; acc.w += w * xpi.w;
    }

    int beg = g_off[i], end = g_off[i + 1];
    const float* salpha_f = (const float*)g_salpha;
    for (int base = beg; base < end; base += 8) {
        int myedge = base + (lane >> 2);
        float w = 0.f;
        if (myedge < end) {
            float a = salpha_f[(size_t)base * 4 + lane] + adst_s;
            a = a > 0.f ? a : 0.2f * a;
            w = __expf(a);
        }
        dsum += w;
        // clamp out-of-range sources to self row (weight is 0 there) -> branch-free gathers
        int sv = i;
        if (lane < 8 && base + lane < end) sv = g_ssrc[base + lane];
        #pragma unroll
        for (int k = 0; k < 8; k++) {
            int s = __shfl_sync(FULLM, sv, k);
            float we = __shfl_sync(FULLM, w, k * 4 + hl);
            float4 xp = g_xproj[(size_t)s * 32 + lane];
            acc.x += we * xp.x; acc.y += we * xp.y;
            acc.z += we * xp.z; acc.w += we * xp.w;
        }
    }
    // reduce dsum across the 8 lanes sharing (lane&3)
    #pragma unroll
    for (int m = 4; m <= 16; m <<= 1) dsum += __shfl_xor_sync(FULLM, dsum, m);
    float denom = __shfl_sync(FULLM, dsum, hl);
    float inv = 1.0f / denom;
    float4 b4 = *(const float4*)(bias + lane * 4);
    float4 o;
    o.x = acc.x * inv + b4.x;
    o.y = acc.y * inv + b4.y;
    o.z = acc.z * inv + b4.z;
    o.w = acc.w * inv + b4.w;
    *(float4*)(out + (size_t)i * KHC + lane * 4) = o;
}

// ---------------- launch ----------------
extern "C" void kernel_launch(void* const* d_in, const int* in_sizes, int n_in,
                              void* d_out, int out_size) {
    const float* x         = (const float*)d_in[0];
    const int*   edge_idx  = (const int*)d_in[1];
    const float* edge_attr = (const float*)d_in[2];
    const float* W         = (const float*)d_in[3];
    const float* att_src   = (const float*)d_in[4];
    const float* att_dst   = (const float*)d_in[5];
    const float* W_edge    = (const float*)d_in[6];
    const float* att_edge  = (const float*)d_in[7];
    const float* bias      = (const float*)d_in[8];
    float* out = (float*)d_out;

    int n = in_sizes[0] / KIN;       // 100000
    int E = in_sizes[1] / 2;         // 1600000
    int nb = (E + 31) / 32;          // scatter blocks

    k_reset<<<(n + 255) / 256, 256>>>(n);
    k_w2<<<1, 256>>>(W_edge, att_edge);
    k_gemm<<<(n + 127) / 128, 256>>>(x, W, n);
    k_attn<<<(n + 7) / 8, 256>>>(att_src, att_dst, n);
    k_hist<<<(E + 255) / 256, 256>>>(edge_idx, E);
    k_scan<<<1, 1024>>>(n);
    k_scatter<<<nb, 256>>>(edge_idx, edge_attr, E);
    k_psum<<<64, 256>>>(nb);
    k_loopae<<<1, 32>>>(E);
    k_agg<<<(n + 7) / 8, 256>>>(bias, out, n);
}

// round 4
// speedup vs baseline: 1.0229x; 1.0229x over previous
#include <cuda_runtime.h>
#include <cuda_bf16.h>
#include <cstdint>

#define KN      100000     // nodes
#define KE      1600000    // edges
#define KIN     256        // in channels
#define KED     64         // edge dim
#define KH      4          // heads
#define KC      32         // channels/head
#define KHC     128        // H*C
#define KNB     ((KE + 31) / 32)   // scatter blocks

#define FULLM 0xFFFFFFFFu

// ---------------- scratch (static device globals; no allocation) ----------------
__device__ float4 g_xproj[KN * 32];        // [N][128] as float4   (51.2 MB)
__device__ float4 g_asrc[KN];              // [N][4]
__device__ float4 g_adst[KN];              // [N][4]
__device__ float  g_W2[KED * KH];          // [64][4]
__device__ float  g_loopsum[KH];
__device__ float  g_loopae[KH];
__device__ int    g_deg[KN];
__device__ int    g_off[KN + 1];
__device__ int    g_cursor[KN];
__device__ int    g_ssrc[KE];
__device__ float4 g_salpha[KE];            // [E][4]  (25.6 MB)
__device__ float4 g_part[KNB];             // per-block p-sums
__device__ __nv_bfloat16 g_xhi[KN * KIN];  // 51.2 MB
__device__ __nv_bfloat16 g_xlo[KN * KIN];  // 51.2 MB
__device__ __nv_bfloat16 g_whi[KIN * KHC];
__device__ __nv_bfloat16 g_wlo[KIN * KHC];

// ---------------- helpers ----------------
__device__ __forceinline__ uint32_t smem_u32(const void* p) {
    return (uint32_t)__cvta_generic_to_shared(p);
}
__device__ __forceinline__ void ldsm_x4(uint32_t& r0, uint32_t& r1, uint32_t& r2, uint32_t& r3,
                                        uint32_t addr) {
    asm volatile("ldmatrix.sync.aligned.m8n8.x4.shared.b16 {%0,%1,%2,%3}, [%4];\n"
                 : "=r"(r0), "=r"(r1), "=r"(r2), "=r"(r3) : "r"(addr));
}
__device__ __forceinline__ void ldsm_x4_t(uint32_t& r0, uint32_t& r1, uint32_t& r2, uint32_t& r3,
                                          uint32_t addr) {
    asm volatile("ldmatrix.sync.aligned.m8n8.x4.trans.shared.b16 {%0,%1,%2,%3}, [%4];\n"
                 : "=r"(r0), "=r"(r1), "=r"(r2), "=r"(r3) : "r"(addr));
}
__device__ __forceinline__ void mma16816(float* d, const uint32_t* a, uint32_t b0, uint32_t b1) {
    asm volatile(
        "mma.sync.aligned.m16n8k16.row.col.f32.bf16.bf16.f32 "
        "{%0,%1,%2,%3},{%4,%5,%6,%7},{%8,%9},{%0,%1,%2,%3};\n"
        : "+f"(d[0]), "+f"(d[1]), "+f"(d[2]), "+f"(d[3])
        : "r"(a[0]), "r"(a[1]), "r"(a[2]), "r"(a[3]), "r"(b0), "r"(b1));
}
__device__ __forceinline__ void cp16(uint32_t dst, const void* src, int sz) {
    asm volatile("cp.async.cg.shared.global [%0], [%1], 16, %2;\n"
                 :: "r"(dst), "l"(src), "r"(sz));
}
__device__ __forceinline__ void cp_commit() { asm volatile("cp.async.commit_group;\n"); }
__device__ __forceinline__ void cp_wait0() { asm volatile("cp.async.wait_group 0;\n"); }

__device__ __forceinline__ uint2 split4(float4 v) {
    // returns {hi bf16x4, lo bf16x4} packed
    float vv[4] = {v.x, v.y, v.z, v.w};
    __nv_bfloat16 h[4], l[4];
    #pragma unroll
    for (int j = 0; j < 4; j++) {
        h[j] = __float2bfloat16(vv[j]);
        l[j] = __float2bfloat16(vv[j] - __bfloat162float(h[j]));
    }
    uint2 r;
    uint16_t* ph = (uint16_t*)&r.x;  // will overwrite both halves
    uint32_t hi, lo;
    uint16_t hb[4], lb[4];
    #pragma unroll
    for (int j = 0; j < 4; j++) { hb[j] = *(uint16_t*)&h[j]; lb[j] = *(uint16_t*)&l[j]; }
    hi = (uint32_t)hb[0] | ((uint32_t)hb[1] << 16);
    lo = (uint32_t)hb[2] | ((uint32_t)hb[3] << 16);
    r.x = hi; r.y = lo;
    (void)ph;
    return r;
}

// ---------------- reset ----------------
__global__ void k_reset(int n) {
    int i = blockIdx.x * blockDim.x + threadIdx.x;
    if (i < n) g_deg[i] = 0;
    if (i < KH) g_loopsum[i] = 0.f;
}

// ---------------- convert x -> bf16 hi/lo ----------------
__global__ void k_xconv(const float* __restrict__ x, int total4) {
    int i = blockIdx.x * blockDim.x + threadIdx.x;
    if (i >= total4) return;
    float4 v = *(const float4*)(x + (size_t)i * 4);
    float vv[4] = {v.x, v.y, v.z, v.w};
    uint16_t hb[4], lb[4];
    #pragma unroll
    for (int j = 0; j < 4; j++) {
        __nv_bfloat16 h = __float2bfloat16(vv[j]);
        __nv_bfloat16 l = __float2bfloat16(vv[j] - __bfloat162float(h));
        hb[j] = *(uint16_t*)&h; lb[j] = *(uint16_t*)&l;
    }
    uint2 ph, pl;
    ph.x = (uint32_t)hb[0] | ((uint32_t)hb[1] << 16);
    ph.y = (uint32_t)hb[2] | ((uint32_t)hb[3] << 16);
    pl.x = (uint32_t)lb[0] | ((uint32_t)lb[1] << 16);
    pl.y = (uint32_t)lb[2] | ((uint32_t)lb[3] << 16);
    *(uint2*)&g_xhi[(size_t)i * 4] = ph;
    *(uint2*)&g_xlo[(size_t)i * 4] = pl;
}

// ---------------- convert W -> bf16 hi/lo ----------------
__global__ void k_wconv(const float* __restrict__ W) {
    int i = blockIdx.x * blockDim.x + threadIdx.x;   // 8192 threads, one float4 each
    if (i >= KIN * KHC / 4) return;
    float4 v = *(const float4*)(W + (size_t)i * 4);
    float vv[4] = {v.x, v.y, v.z, v.w};
    uint16_t hb[4], lb[4];
    #pragma unroll
    for (int j = 0; j < 4; j++) {
        __nv_bfloat16 h = __float2bfloat16(vv[j]);
        __nv_bfloat16 l = __float2bfloat16(vv[j] - __bfloat162float(h));
        hb[j] = *(uint16_t*)&h; lb[j] = *(uint16_t*)&l;
    }
    uint2 ph, pl;
    ph.x = (uint32_t)hb[0] | ((uint32_t)hb[1] << 16);
    ph.y = (uint32_t)hb[2] | ((uint32_t)hb[3] << 16);
    pl.x = (uint32_t)lb[0] | ((uint32_t)lb[1] << 16);
    pl.y = (uint32_t)lb[2] | ((uint32_t)lb[3] << 16);
    *(uint2*)&g_whi[(size_t)i * 4] = ph;
    *(uint2*)&g_wlo[(size_t)i * 4] = pl;
}

// ---------------- W2[d][h] = sum_c W_edge[d, h*32+c] * att_edge[h, c] ----------------
__global__ void k_w2(const float* __restrict__ W_edge, const float* __restrict__ att_edge) {
    int t = threadIdx.x;                 // 256 threads
    int d = t >> 2, h = t & 3;
    float s = 0.f;
    #pragma unroll 8
    for (int c = 0; c < KC; c++)
        s += W_edge[d * KHC + h * KC + c] * att_edge[h * KC + c];
    g_W2[d * KH + h] = s;
}

// ---------------- GEMM: x_proj = x[N,256] @ W[256,128], bf16-split HMMA ----------------
// 8 warps (4 m-warps x 2 n-warps). Tile 128x128, k-chunk 16, double-buffered cp.async.
#define AP 24   // A row stride (bf16): 48B = 3x16B, coprime with 8 -> LDSM conflict-free
#define BP 136  // B row stride: 272B = 17x16B, coprime with 8
__global__ __launch_bounds__(256) void k_gemm(int n) {
    __shared__ __nv_bfloat16 As[2][2][128][AP];   // [stage][part][m][k] 24KB
    __shared__ __nv_bfloat16 Bs[2][2][16][BP];    // [stage][part][k][n] 17.4KB

    int tid = threadIdx.x;
    int lane = tid & 31;
    int wid = tid >> 5;
    int warp_m = wid & 3;
    int warp_n = wid >> 2;
    int m0 = warp_m * 32;
    int n0w = warp_n * 64;
    int bm = blockIdx.x * 128;
    int g = lane >> 2, t = lane & 3;

    float acc[2][8][4];
    #pragma unroll
    for (int mi = 0; mi < 2; mi++)
        #pragma unroll
        for (int ni = 0; ni < 8; ni++)
            #pragma unroll
            for (int r = 0; r < 4; r++) acc[mi][ni][r] = 0.f;

    int a_row = lane & 15;
    int a_koff = (lane >> 4) * 8;
    int b_krow = (lane & 7) + ((lane >> 3) & 1) * 8;
    int b_noff = (lane >> 4) * 8;

    // per-thread load tasks
    int lrow = tid >> 1, lseg = tid & 1;          // A: 128 rows x 2 segs
    int lk = tid >> 4, lns = tid & 15;            // B: 16 rows x 16 segs

    int gm = bm + lrow;
    int asz = (gm < n) ? 16 : 0;
    size_t arow_off = (size_t)(gm < n ? gm : 0) * KIN + lseg * 8;

    // prologue: chunk 0 into stage 0
    {
        cp16(smem_u32(&As[0][0][lrow][lseg * 8]), &g_xhi[arow_off], asz);
        cp16(smem_u32(&As[0][1][lrow][lseg * 8]), &g_xlo[arow_off], asz);
        cp16(smem_u32(&Bs[0][0][lk][lns * 8]), &g_whi[(size_t)lk * KHC + lns * 8], 16);
        cp16(smem_u32(&Bs[0][1][lk][lns * 8]), &g_wlo[(size_t)lk * KHC + lns * 8], 16);
        cp_commit();
    }

    #pragma unroll 1
    for (int c = 0; c < 16; c++) {
        cp_wait0();
        __syncthreads();
        if (c < 15) {
            int kb = (c + 1) * 16;
            int s = (c + 1) & 1;
            cp16(smem_u32(&As[s][0][lrow][lseg * 8]), &g_xhi[arow_off + kb], asz);
            cp16(smem_u32(&As[s][1][lrow][lseg * 8]), &g_xlo[arow_off + kb], asz);
            cp16(smem_u32(&Bs[s][0][lk][lns * 8]), &g_whi[(size_t)(kb + lk) * KHC + lns * 8], 16);
            cp16(smem_u32(&Bs[s][1][lk][lns * 8]), &g_wlo[(size_t)(kb + lk) * KHC + lns * 8], 16);
            cp_commit();
        }
        int s = c & 1;
        uint32_t af[2][2][4];
        #pragma unroll
        for (int part = 0; part < 2; part++)
            #pragma unroll
            for (int mi = 0; mi < 2; mi++) {
                uint32_t addr = smem_u32(&As[s][part][m0 + mi * 16 + a_row][a_koff]);
                ldsm_x4(af[part][mi][0], af[part][mi][1], af[part][mi][2], af[part][mi][3], addr);
            }
        #pragma unroll
        for (int np = 0; np < 4; np++) {
            uint32_t bh[4], bl[4];
            {
                uint32_t addr = smem_u32(&Bs[s][0][b_krow][n0w + np * 16 + b_noff]);
                ldsm_x4_t(bh[0], bh[1], bh[2], bh[3], addr);
            }
            {
                uint32_t addr = smem_u32(&Bs[s][1][b_krow][n0w + np * 16 + b_noff]);
                ldsm_x4_t(bl[0], bl[1], bl[2], bl[3], addr);
            }
            #pragma unroll
            for (int half = 0; half < 2; half++) {
                int ni = np * 2 + half;
                #pragma unroll
                for (int mi = 0; mi < 2; mi++) {
                    mma16816(acc[mi][ni], af[0][mi], bh[half * 2], bh[half * 2 + 1]);
                    mma16816(acc[mi][ni], af[1][mi], bh[half * 2], bh[half * 2 + 1]);
                    mma16816(acc[mi][ni], af[0][mi], bl[half * 2], bl[half * 2 + 1]);
                }
            }
        }
        __syncthreads();
    }

    // ---- epilogue ----
    float* gx = (float*)g_xproj;
    #pragma unroll
    for (int mi = 0; mi < 2; mi++) {
        #pragma unroll
        for (int ni = 0; ni < 8; ni++) {
            int col = n0w + ni * 8 + t * 2;
            int r0 = bm + m0 + mi * 16 + g;
            int r1 = r0 + 8;
            if (r0 < n) {
                float2 v; v.x = acc[mi][ni][0]; v.y = acc[mi][ni][1];
                *(float2*)&gx[(size_t)r0 * KHC + col] = v;
            }
            if (r1 < n) {
                float2 v; v.x = acc[mi][ni][2]; v.y = acc[mi][ni][3];
                *(float2*)&gx[(size_t)r1 * KHC + col] = v;
            }
        }
    }
}

// ---------------- a_src / a_dst: warp per node ----------------
__global__ void k_attn(const float* __restrict__ att_src,
                       const float* __restrict__ att_dst, int n) {
    int warp = (blockIdx.x * blockDim.x + threadIdx.x) >> 5;
    int lane = threadIdx.x & 31;
    if (warp >= n) return;
    float4 xp = g_xproj[(size_t)warp * 32 + lane];
    float4 as = *(const float4*)(att_src + lane * 4);
    float4 ad = *(const float4*)(att_dst + lane * 4);
    float ds = xp.x * as.x + xp.y * as.y + xp.z * as.z + xp.w * as.w;
    float dd = xp.x * ad.x + xp.y * ad.y + xp.z * ad.z + xp.w * ad.w;
    #pragma unroll
    for (int m = 1; m <= 4; m <<= 1) {
        ds += __shfl_xor_sync(FULLM, ds, m);
        dd += __shfl_xor_sync(FULLM, dd, m);
    }
    if ((lane & 7) == 0) {
        int h = lane >> 3;
        ((float*)&g_asrc[warp])[h] = ds;
        ((float*)&g_adst[warp])[h] = dd;
    }
}

// ---------------- histogram of dst ----------------
__global__ void k_hist(const int* __restrict__ edge_index, int E) {
    int e = blockIdx.x * blockDim.x + threadIdx.x;
    if (e < E) atomicAdd(&g_deg[edge_index[E + e]], 1);
}

// ---------------- single-block scan ----------------
__global__ void k_scan(int n) {
    __shared__ int s[1024];
    int t = threadIdx.x;
    int chunk = (n + 1023) / 1024;
    int start = t * chunk;
    int sum = 0;
    for (int j = 0; j < chunk; j++) {
        int i = start + j;
        if (i < n) sum += g_deg[i];
    }
    s[t] = sum;
    __syncthreads();
    for (int o = 1; o < 1024; o <<= 1) {
        int v = (t >= o) ? s[t - o] : 0;
        __syncthreads();
        s[t] += v;
        __syncthreads();
    }
    int run = s[t] - sum;
    for (int j = 0; j < chunk; j++) {
        int i = start + j;
        if (i < n) {
            g_off[i] = run;
            g_cursor[i] = run;
            run += g_deg[i];
        }
    }
    if (t == 1023) g_off[n] = s[1023];
}

// ---------------- scatter: 8 lanes per edge (4 edges/warp) ----------------
__global__ __launch_bounds__(256) void k_scatter(const int* __restrict__ edge_index,
                                                 const float* __restrict__ edge_attr, int E) {
    __shared__ float Ws2[KED * KH];
    __shared__ float bp[KH];
    int tid = threadIdx.x;
    Ws2[tid] = g_W2[tid];
    if (tid < KH) bp[tid] = 0.f;
    __syncthreads();

    int lane = tid & 31;
    int wid = tid >> 5;
    int g8 = lane >> 3, l8 = lane & 7;
    int e = blockIdx.x * 32 + wid * 4 + g8;

    float p0 = 0.f, p1 = 0.f, p2 = 0.f, p3 = 0.f;
    if (e < E) {
        const float* ea = edge_attr + (size_t)e * KED + l8 * 8;
        float4 v0 = *(const float4*)ea;
        float4 v1 = *(const float4*)(ea + 4);
        float av[8] = {v0.x, v0.y, v0.z, v0.w, v1.x, v1.y, v1.z, v1.w};
        int db = l8 * 8;
        #pragma unroll
        for (int j = 0; j < 8; j++) {
            const float* w = &Ws2[(db + j) * 4];
            p0 += av[j] * w[0];
            p1 += av[j] * w[1];
            p2 += av[j] * w[2];
            p3 += av[j] * w[3];
        }
    }
    #pragma unroll
    for (int m = 1; m <= 4; m <<= 1) {
        p0 += __shfl_xor_sync(FULLM, p0, m);
        p1 += __shfl_xor_sync(FULLM, p1, m);
        p2 += __shfl_xor_sync(FULLM, p2, m);
        p3 += __shfl_xor_sync(FULLM, p3, m);
    }
    if (l8 == 0 && e < E) {
        atomicAdd(&bp[0], p0);
        atomicAdd(&bp[1], p1);
        atomicAdd(&bp[2], p2);
        atomicAdd(&bp[3], p3);
        int src = edge_index[e];
        int dst = edge_index[E + e];
        float4 as = g_asrc[src];
        int pos = atomicAdd(&g_cursor[dst], 1);
        g_ssrc[pos] = src;
        g_salpha[pos] = make_float4(as.x + p0, as.y + p1, as.z + p2, as.w + p3);
    }
    __syncthreads();
    if (tid < KH) ((float*)&g_part[blockIdx.x])[tid] = bp[tid];
}

// ---------------- reduce per-block p-sums ----------------
__global__ void k_psum(int nb) {
    int tid = blockIdx.x * blockDim.x + threadIdx.x;
    int stride = gridDim.x * blockDim.x;
    float4 s = make_float4(0.f, 0.f, 0.f, 0.f);
    for (int j = tid; j < nb; j += stride) {
        float4 v = g_part[j];
        s.x += v.x; s.y += v.y; s.z += v.z; s.w += v.w;
    }
    #pragma unroll
    for (int m = 16; m >= 1; m >>= 1) {
        s.x += __shfl_xor_sync(FULLM, s.x, m);
        s.y += __shfl_xor_sync(FULLM, s.y, m);
        s.z += __shfl_xor_sync(FULLM, s.z, m);
        s.w += __shfl_xor_sync(FULLM, s.w, m);
    }
    __shared__ float4 ws[8];
    int warp = threadIdx.x >> 5;
    int lane = threadIdx.x & 31;
    if (lane == 0) ws[warp] = s;
    __syncthreads();
    if (warp == 0) {
        float4 v = (lane < 8) ? ws[lane] : make_float4(0.f, 0.f, 0.f, 0.f);
        #pragma unroll
        for (int m = 4; m >= 1; m >>= 1) {
            v.x += __shfl_xor_sync(FULLM, v.x, m);
            v.y += __shfl_xor_sync(FULLM, v.y, m);
            v.z += __shfl_xor_sync(FULLM, v.z, m);
            v.w += __shfl_xor_sync(FULLM, v.w, m);
        }
        if (lane == 0) {
            atomicAdd(&g_loopsum[0], v.x);
            atomicAdd(&g_loopsum[1], v.y);
            atomicAdd(&g_loopsum[2], v.z);
            atomicAdd(&g_loopsum[3], v.w);
        }
    }
}

// ---------------- loop a_edge = psum / E ----------------
__global__ void k_loopae(int E) {
    int h = threadIdx.x;
    if (h < KH) g_loopae[h] = g_loopsum[h] / (float)E;
}

// ---------------- aggregation: warp per node, fused softmax + weighted sum ----------------
__global__ __launch_bounds__(256) void k_agg(const float* __restrict__ bias,
                                             float* __restrict__ out, int n) {
    int i = (blockIdx.x * blockDim.x + threadIdx.x) >> 5;
    int lane = threadIdx.x & 31;
    if (i >= n) return;

    int hl = lane >> 3;     // head for accumulation lanes
    int sub = lane & 3;     // head for exp lanes

    float adst_s = ((const float*)&g_adst[i])[sub];
    float asrc_s = ((const float*)&g_asrc[i])[sub];
    float lae_s  = g_loopae[sub];
    float4 xpi = g_xproj[(size_t)i * 32 + lane];

    float4 acc = make_float4(0.f, 0.f, 0.f, 0.f);
    float dsum = 0.f;

    // self loop
    float vs = asrc_s + adst_s + lae_s;
    vs = vs > 0.f ? vs : 0.2f * vs;
    float ws = __expf(vs);
    if (lane < 4) dsum += ws;
    {
        float w = __shfl_sync(FULLM, ws, hl);
        acc.x += w * xpi.x; acc.y += w * xpi.y; acc.z += w * xpi.z; acc.w += w * xpi.w;
    }

    int beg = g_off[i], end = g_off[i + 1];
    const float* salpha_f = (const float*)g_salpha;
    for (int base = beg; base < end; base += 8) {
        int myedge = base + (lane >> 2);
        float w = 0.f;
        if (myedge < end) {
            float a = salpha_f[(size_t)base * 4 + lane] + adst_s;
            a = a > 0.f ? a : 0.2f * a;
            w = __expf(a);
        }
        dsum += w;
        // clamp out-of-range sources to self row (weight is 0 there) -> branch-free gathers
        int sv = i;
        if (lane < 8 && base + lane < end) sv = g_ssrc[base + lane];
        #pragma unroll
        for (int k = 0; k < 8; k++) {
            int s = __shfl_sync(FULLM, sv, k);
            float we = __shfl_sync(FULLM, w, k * 4 + hl);
            float4 xp = g_xproj[(size_t)s * 32 + lane];
            acc.x += we * xp.x; acc.y += we * xp.y;
            acc.z += we * xp.z; acc.w += we * xp.w;
        }
    }
    // reduce dsum across the 8 lanes sharing (lane&3)
    #pragma unroll
    for (int m = 4; m <= 16; m <<= 1) dsum += __shfl_xor_sync(FULLM, dsum, m);
    float denom = __shfl_sync(FULLM, dsum, hl);
    float inv = 1.0f / denom;
    float4 b4 = *(const float4*)(bias + lane * 4);
    float4 o;
    o.x = acc.x * inv + b4.x;
    o.y = acc.y * inv + b4.y;
    o.z = acc.z * inv + b4.z;
    o.w = acc.w * inv + b4.w;
    *(float4*)(out + (size_t)i * KHC + lane * 4) = o;
}

// ---------------- launch ----------------
extern "C" void kernel_launch(void* const* d_in, const int* in_sizes, int n_in,
                              void* d_out, int out_size) {
    const float* x         = (const float*)d_in[0];
    const int*   edge_idx  = (const int*)d_in[1];
    const float* edge_attr = (const float*)d_in[2];
    const float* W         = (const float*)d_in[3];
    const float* att_src   = (const float*)d_in[4];
    const float* att_dst   = (const float*)d_in[5];
    const float* W_edge    = (const float*)d_in[6];
    const float* att_edge  = (const float*)d_in[7];
    const float* bias      = (const float*)d_in[8];
    float* out = (float*)d_out;

    int n = in_sizes[0] / KIN;       // 100000
    int E = in_sizes[1] / 2;         // 1600000
    int nb = (E + 31) / 32;          // scatter blocks
    int t4 = n * (KIN / 4);          // float4 count for xconv

    k_reset<<<(n + 255) / 256, 256>>>(n);
    k_w2<<<1, 256>>>(W_edge, att_edge);
    k_wconv<<<(KIN * KHC / 4 + 255) / 256, 256>>>(W);
    k_xconv<<<(t4 + 255) / 256, 256>>>(x, t4);
    k_gemm<<<(n + 127) / 128, 256>>>(n);
    k_attn<<<(n + 7) / 8, 256>>>(att_src, att_dst, n);
    k_hist<<<(E + 255) / 256, 256>>>(edge_idx, E);
    k_scan<<<1, 1024>>>(n);
    k_scatter<<<nb, 256>>>(edge_idx, edge_attr, E);
    k_psum<<<64, 256>>>(nb);
    k_loopae<<<1, 32>>>(E);
    k_agg<<<(n + 7) / 8, 256>>>(bias, out, n);
}